// round 17
// baseline (speedup 1.0000x reference)
#include <cuda_runtime.h>
#include <cuda_bf16.h>
#include <cuda_fp16.h>
#include <cstdint>
#include <math.h>

// Problem constants
#define N_ENT 100000
#define N_REL 1000
#define RANK  256
#define TWO_R 512
#define BATCH 1024
#define MAX_NB 50

// Output layout (flattened tuple): scores, n_lhs, n_rel, n_rhs, n_gec
#define OFF_SCORES 0
#define OFF_NLHS   ((size_t)BATCH * N_ENT)
#define OFF_NREL   (OFF_NLHS + (size_t)BATCH * RANK)
#define OFF_NRHS   (OFF_NREL + (size_t)BATCH * RANK)
#define OFF_NGEC   (OFF_NRHS + (size_t)BATCH * RANK)

// Power-of-2 scaling for fp16 GEMM (exact, no extra rounding)
#define SCALE_Q 1048576.0f            // 2^20
#define SCALE_E 1024.0f               // 2^10
#define SCALE_OUT 9.313225746154785e-10f   // 2^-30

#define BR (BATCH * RANK)

// Scratch (static device globals; no allocation allowed)
#define K1_SPLIT 4
#define K3_SPLIT 8
__device__ float g_w0 [K1_SPLIT * BR];
__device__ float g_w1 [K1_SPLIT * BR];
__device__ float g_ec0[BR];
__device__ float g_ec1[BR];
__device__ float g_en0[K3_SPLIT * BR];
__device__ float g_en1[K3_SPLIT * BR];

// scaled fp16 Q for the big GEMM (E converted inside k4)
__device__ __half g_Qf[BATCH * TWO_R];

// ===========================================================================
// PTX helpers (compute_103-safe subset: cp.async / ldmatrix / mma.sync only)
// ===========================================================================
__device__ __forceinline__ uint32_t smem_to_u32(const void* smem_ptr) {
    uint32_t addr;
    asm("{ .reg .u64 tmp; cvta.to.shared.u64 tmp, %1; cvt.u32.u64 %0, tmp; }"
        : "=r"(addr) : "l"(smem_ptr));
    return addr;
}

#define CP_ASYNC16(smem_u32, gptr) \
    asm volatile("cp.async.cg.shared.global [%0], [%1], 16;" \
        :: "r"(smem_u32), "l"(gptr) : "memory")

#define CP_ASYNC_COMMIT() \
    asm volatile("cp.async.commit_group;" ::: "memory")

#define CP_ASYNC_WAIT_GROUP(n) \
    asm volatile("cp.async.wait_group %0;" :: "n"(n) : "memory")

// Producer-scope barrier: cp.async data loaded by one producer thread is
// read by a DIFFERENT producer thread in convert; wait_group alone only
// guarantees visibility to the issuing thread. (This was the R14 race.)
#define PRODUCER_BAR() \
    asm volatile("bar.sync 1, 128;" ::: "memory")

__device__ __forceinline__ void ldsm_x4(uint32_t r[4], uint32_t addr) {
    asm volatile("ldmatrix.sync.aligned.m8n8.x4.shared.b16 {%0,%1,%2,%3}, [%4];"
        : "=r"(r[0]), "=r"(r[1]), "=r"(r[2]), "=r"(r[3]) : "r"(addr));
}

__device__ __forceinline__ void mma_16816_f16(
    float c[4], const uint32_t a[4], uint32_t b0, uint32_t b1)
{
    asm volatile(
        "mma.sync.aligned.m16n8k16.row.col.f32.f16.f16.f32 "
        "{%0,%1,%2,%3}, {%4,%5,%6,%7}, {%8,%9}, {%0,%1,%2,%3};"
        : "+f"(c[0]), "+f"(c[1]), "+f"(c[2]), "+f"(c[3])
        : "r"(a[0]), "r"(a[1]), "r"(a[2]), "r"(a[3]), "r"(b0), "r"(b1));
}

__device__ __forceinline__ uint32_t h2_to_u32(__half2 h) {
    uint32_t u;
    *reinterpret_cast<__half2*>(&u) = h;
    return u;
}

// ---------------------------------------------------------------------------
// K1: split-K (4-way) partial of w0/w1. Block = (batch-group, j-quarter).
// ---------------------------------------------------------------------------
#define K1_ROWS 4
#define K1_J (TWO_R / K1_SPLIT)   // 128
__global__ __launch_bounds__(256) void k1_wproj(
    const int* __restrict__ x,
    const float* __restrict__ E_ent, const float* __restrict__ E_rel,
    const float* __restrict__ W0, const float* __restrict__ W1,
    const float* __restrict__ bw0, const float* __restrict__ bw1)
{
    const int bid = blockIdx.x;
    const int split = bid & (K1_SPLIT - 1);
    const int b0 = (bid >> 2) * K1_ROWS;
    const int tid = threadIdx.x;

    __shared__ float t0s[K1_ROWS][K1_J];
    __shared__ float t1s[K1_ROWS][K1_J];

    const int src = split >> 1;          // 0 -> lhs (E_ent), 1 -> rel (E_rel)
    const int off = (split & 1) * K1_J;  // 0 or 128 within the rank half
    for (int rr = 0; rr < K1_ROWS; rr++) {
        const int b = b0 + rr;
        const size_t row_idx = (size_t)x[b * 3 + src];
        const float* row = (src == 0 ? E_ent : E_rel) + row_idx * TWO_R;
        if (tid < K1_J) t0s[rr][tid] = row[off + tid];
        else            t1s[rr][tid - K1_J] = row[RANK + off + (tid - K1_J)];
    }
    __syncthreads();

    const int k = tid;
    float a0[K1_ROWS], a1[K1_ROWS];
#pragma unroll
    for (int rr = 0; rr < K1_ROWS; rr++) { a0[rr] = 0.f; a1[rr] = 0.f; }

#pragma unroll 8
    for (int j = 0; j < K1_J; j++) {
        const int jj = split * K1_J + j;
        const float w0jk = W0[jj * RANK + k];
        const float w1jk = W1[jj * RANK + k];
#pragma unroll
        for (int rr = 0; rr < K1_ROWS; rr++) {
            const float a = t0s[rr][j];
            const float c = t1s[rr][j];
            a0[rr] += a * w0jk - c * w1jk;
            a1[rr] += a * w1jk + c * w0jk;
        }
    }
    const float b0k = split == 0 ? bw0[k] : 0.f;
    const float b1k = split == 0 ? bw1[k] : 0.f;
#pragma unroll
    for (int rr = 0; rr < K1_ROWS; rr++) {
        g_w0[split * BR + (b0 + rr) * RANK + k] = a0[rr] + b0k;
        g_w1[split * BR + (b0 + rr) * RANK + k] = a1[rr] + b1k;
    }
}

// ---------------------------------------------------------------------------
// K2: logits over 50 neighbors, softmax, ec0/ec1 weighted sums.
// ---------------------------------------------------------------------------
#define K2_SMEM (MAX_NB * TWO_R * 4)   // 102400
__global__ __launch_bounds__(256) void k2_attn(
    const int* __restrict__ nb_idx, const float* __restrict__ E_ent)
{
    extern __shared__ __align__(16) float nbs[];   // [MAX_NB][TWO_R]
    __shared__ float w0s[RANK], w1s[RANK];
    __shared__ float logit_s[MAX_NB];
    __shared__ float alpha_s[MAX_NB];
    __shared__ int   idx_s[MAX_NB];

    const int b = blockIdx.x;
    const int tid = threadIdx.x;
    const int wid = tid >> 5;
    const int lane = tid & 31;

    {
        const int ik = b * RANK + tid;
        w0s[tid] = (g_w0[ik] + g_w0[BR + ik]) + (g_w0[2 * BR + ik] + g_w0[3 * BR + ik]);
        w1s[tid] = (g_w1[ik] + g_w1[BR + ik]) + (g_w1[2 * BR + ik] + g_w1[3 * BR + ik]);
    }
    if (tid < MAX_NB) idx_s[tid] = nb_idx[b * MAX_NB + tid];
    __syncthreads();

    const uint32_t nbs_u = smem_to_u32(nbs);
    for (int u = tid; u < MAX_NB * 128; u += 256) {
        const int m = u >> 7;
        const int q = u & 127;
        CP_ASYNC16(nbs_u + (uint32_t)u * 16,
                   E_ent + (size_t)idx_s[m] * TWO_R + q * 4);
    }
    CP_ASYNC_COMMIT();
    CP_ASYNC_WAIT_GROUP(0);
    __syncthreads();

    for (int m = wid; m < MAX_NB; m += 8) {
        const float* row = nbs + m * TWO_R;
        float s = 0.f;
#pragma unroll
        for (int k = lane; k < RANK; k += 32)
            s += w0s[k] * row[k] - w1s[k] * row[RANK + k];
#pragma unroll
        for (int o = 16; o > 0; o >>= 1) s += __shfl_xor_sync(0xffffffffu, s, o);
        if (lane == 0) logit_s[m] = s;
    }
    __syncthreads();

    if (tid == 0) {
        float mx = logit_s[0];
        for (int m = 1; m < MAX_NB; m++) mx = fmaxf(mx, logit_s[m]);
        float sum = 0.f;
        for (int m = 0; m < MAX_NB; m++) { float e = __expf(logit_s[m] - mx); alpha_s[m] = e; sum += e; }
        const float inv = 1.0f / sum;
        for (int m = 0; m < MAX_NB; m++) alpha_s[m] *= inv;
    }
    __syncthreads();

    const int k = tid;
    float acc0 = 0.f, acc1 = 0.f;
#pragma unroll 10
    for (int m = 0; m < MAX_NB; m++) {
        const float a = alpha_s[m];
        acc0 += a * nbs[m * TWO_R + k];
        acc1 += a * nbs[m * TWO_R + RANK + k];
    }
    g_ec0[b * RANK + k] = acc0;
    g_ec1[b * RANK + k] = acc1;
}

// ---------------------------------------------------------------------------
// K3a: split-K (8-way) partial of ec projection, 8 rows/block.
// ---------------------------------------------------------------------------
#define K3_ROWS 8
#define K3_J (RANK / K3_SPLIT)   // 32
__global__ __launch_bounds__(256) void k3a_ecproj(
    const float* __restrict__ W20, const float* __restrict__ W21,
    const float* __restrict__ bw20, const float* __restrict__ bw21)
{
    const int bid = blockIdx.x;
    const int split = bid & (K3_SPLIT - 1);
    const int b0 = (bid >> 3) * K3_ROWS;
    const int tid = threadIdx.x;

    __shared__ float e0s[K3_ROWS][K3_J];
    __shared__ float e1s[K3_ROWS][K3_J];

#pragma unroll
    for (int v = tid; v < 2 * K3_ROWS * K3_J; v += 256) {
        const int arr = v >> 8;
        const int rem = v & 255;
        const int rr  = rem >> 5;
        const int j   = rem & 31;
        const float val = (arr == 0 ? g_ec0 : g_ec1)[(b0 + rr) * RANK + split * K3_J + j];
        if (arr == 0) e0s[rr][j] = val; else e1s[rr][j] = val;
    }
    __syncthreads();

    const int k = tid;
    float a0[K3_ROWS], a1[K3_ROWS];
#pragma unroll
    for (int rr = 0; rr < K3_ROWS; rr++) { a0[rr] = 0.f; a1[rr] = 0.f; }

#pragma unroll 4
    for (int j = 0; j < K3_J; j++) {
        const int jj = split * K3_J + j;
        const float w20 = W20[jj * RANK + k];
        const float w21 = W21[jj * RANK + k];
#pragma unroll
        for (int rr = 0; rr < K3_ROWS; rr++) {
            const float a = e0s[rr][j];
            const float c = e1s[rr][j];
            a0[rr] += a * w20 - c * w21;
            a1[rr] += a * w21 + c * w20;
        }
    }
    const float b20 = split == 0 ? bw20[k] : 0.f;
    const float b21 = split == 0 ? bw21[k] : 0.f;
#pragma unroll
    for (int rr = 0; rr < K3_ROWS; rr++) {
        g_en0[split * BR + (b0 + rr) * RANK + k] = a0[rr] + b20;
        g_en1[split * BR + (b0 + rr) * RANK + k] = a1[rr] + b21;
    }
}

// ---------------------------------------------------------------------------
// K3b: gate scalar, gec, q_re/q_im (scaled fp16 into g_Qf), norms.
// ---------------------------------------------------------------------------
__global__ __launch_bounds__(256) void k3b_gate_q(
    const int* __restrict__ x,
    const float* __restrict__ E_ent, const float* __restrict__ E_rel,
    const float* __restrict__ Uo0, const float* __restrict__ Uo1,
    const float* __restrict__ Wo0, const float* __restrict__ b_g,
    float* __restrict__ out)
{
    __shared__ float warp_part[8];
    __shared__ float g_sh2;
    const int b = blockIdx.x;
    const int k = threadIdx.x;
    const int wid = k >> 5, lane = k & 31;

    const size_t lhs = (size_t)x[b * 3 + 0];
    const size_t rel = (size_t)x[b * 3 + 1];
    const size_t rhs = (size_t)x[b * 3 + 2];

    const float l0 = E_ent[lhs * TWO_R + k];
    const float l1 = E_ent[lhs * TWO_R + RANK + k];
    const float r0 = E_rel[rel * TWO_R + k];
    const float r1 = E_rel[rel * TWO_R + RANK + k];
    const float o0 = E_ent[rhs * TWO_R + k];
    const float o1 = E_ent[rhs * TWO_R + RANK + k];

    const int ik = b * RANK + k;
    float en0 = 0.f, en1 = 0.f;
#pragma unroll
    for (int s = 0; s < K3_SPLIT; s++) {
        en0 += g_en0[s * BR + ik];
        en1 += g_en1[s * BR + ik];
    }

    const float sr = l0 * r0 - l1 * r1;
    const float si = l1 * r0 + l0 * r1;

    float p = sr * Uo0[k] - si * Uo1[k] + en0 * Wo0[k];
#pragma unroll
    for (int o = 16; o > 0; o >>= 1) p += __shfl_xor_sync(0xffffffffu, p, o);
    if (lane == 0) warp_part[wid] = p;
    __syncthreads();
    if (k == 0) {
        float tot = 0.f;
#pragma unroll
        for (int w = 0; w < 8; w++) tot += warp_part[w];
        tot += b_g[0];
        g_sh2 = 1.0f / (1.0f + __expf(-tot));
    }
    __syncthreads();
    const float g = g_sh2;

    const float gec0 = g * en0 + (1.0f - g);
    const float gec1 = g * en1;

    const float q_re = sr * gec0 + si * gec1;
    const float q_im = si * gec0 - sr * gec1;

    g_Qf[b * TWO_R + k]        = __float2half_rn(q_re * SCALE_Q);
    g_Qf[b * TWO_R + RANK + k] = __float2half_rn(q_im * SCALE_Q);

    const size_t nk = (size_t)b * RANK + k;
    out[OFF_NLHS + nk] = sqrtf(l0 * l0 + l1 * l1);
    out[OFF_NREL + nk] = sqrtf(r0 * r0 + r1 * r1);
    out[OFF_NRHS + nk] = sqrtf(o0 * o0 + o1 * o1);
    out[OFF_NGEC + nk] = sqrtf(gec0 * gec0 + gec1 * gec1);
}

// ---------------------------------------------------------------------------
// K4 (fused): scores = Qf (fp16) @ (E_ent*2^10 -> fp16)^T.
// 8 consumer warps (HMMA, CTA tile 128x192, warp 64x48) + 4 producer warps
// (cp.async fp32 E -> staging -> convert -> fp16 tile). Persistent CTAs,
// continuous chunk stream. Producer-scope bar.sync between wait_group and
// convert fixes the cross-thread cp.async visibility race.
// ---------------------------------------------------------------------------
#define NCHUNK 8
#define TILE_N 192
#define NTILE_M (BATCH / 128)                     // 8
#define NTILE_N ((N_ENT + TILE_N - 1) / TILE_N)   // 521
#define NTILES  (NTILE_M * NTILE_N)               // 4168
#define A_TILE_B   (128 * 144)      // 18432
#define B16_TILE_B (TILE_N * 144)   // 27648
#define S_TILE_B   (TILE_N * 272)   // 52224
#define AOFF 0
#define BOFF (3 * A_TILE_B)                 // 55296
#define SOFF (BOFF + 2 * B16_TILE_B)        // 110592
#define SMEM_K4 (SOFF + 2 * S_TILE_B)       // 215040
#define K4_THREADS 384

// Producer: issue cp.async loads for stream position p.
__device__ __forceinline__ void k4_load_pos(
    uint32_t sbase, int p, int bidx, int gridx,
    const __half* Qf, const float* E, int pt)
{
    const int T = bidx + (p >> 3) * gridx;
    const int chunk = p & 7;
    const int m0 = (T & (NTILE_M - 1)) * 128;
    const int n0 = (T / NTILE_M) * TILE_N;
    const int k0 = chunk * 64;
    const uint32_t aS = sbase + AOFF + (uint32_t)(p % 3) * A_TILE_B;
    const uint32_t sS = sbase + SOFF + (uint32_t)(p & 1) * S_TILE_B;
#pragma unroll
    for (int u = 0; u < 8; u++) {
        const int idx = pt + u * 128;       // 0..1023
        const int row = idx >> 3;
        const int g   = idx & 7;
        CP_ASYNC16(aS + (uint32_t)(row * 144 + g * 16),
                   Qf + (size_t)(m0 + row) * TWO_R + k0 + g * 8);
    }
#pragma unroll
    for (int u = 0; u < 24; u++) {
        const int idx = pt + u * 128;       // 0..3071
        const int row = idx >> 4;
        const int q   = idx & 15;
        int er = n0 + row; if (er >= N_ENT) er = N_ENT - 1;
        CP_ASYNC16(sS + (uint32_t)(row * 272 + q * 16),
                   E + (size_t)er * TWO_R + k0 + q * 4);
    }
}

// Producer: convert staging (fp32, pos p) -> fp16 B tile (slot p%2), x SCALE_E
__device__ __forceinline__ void k4_convert(char* smem, int p, int pt)
{
    char* sS = smem + SOFF + (size_t)(p & 1) * S_TILE_B;
    char* bS = smem + BOFF + (size_t)(p & 1) * B16_TILE_B;
#pragma unroll
    for (int s = 0; s < 3; s++) {
        const int u = pt + s * 128;         // 0..383
        const int half = (u >= TILE_N) ? 1 : 0;
        const int row  = u - half * TILE_N;
        const float4* src = (const float4*)(sS + row * 272 + half * 128);
        uint4* dst = (uint4*)(bS + row * 144 + half * 64);
#pragma unroll
        for (int q2 = 0; q2 < 4; q2++) {
            const float4 f0 = src[q2 * 2];
            const float4 f1 = src[q2 * 2 + 1];
            uint4 o;
            o.x = h2_to_u32(__floats2half2_rn(f0.x * SCALE_E, f0.y * SCALE_E));
            o.y = h2_to_u32(__floats2half2_rn(f0.z * SCALE_E, f0.w * SCALE_E));
            o.z = h2_to_u32(__floats2half2_rn(f1.x * SCALE_E, f1.y * SCALE_E));
            o.w = h2_to_u32(__floats2half2_rn(f1.z * SCALE_E, f1.w * SCALE_E));
            dst[q2] = o;
        }
    }
}

__global__ __launch_bounds__(K4_THREADS, 1) void k4_hmma(
    const __half* __restrict__ Qf, const float* __restrict__ E,
    float* __restrict__ C)
{
    extern __shared__ __align__(1024) char smem[];
    const uint32_t sbase = smem_to_u32(smem);
    const int tid  = threadIdx.x;
    const int wid  = tid >> 5;
    const int lane = tid & 31;
    const bool producer = (wid >= 8);
    const int pt = tid - 256;              // producer thread id 0..127
    const int bidx = blockIdx.x;
    const int gridx = gridDim.x;

    const int ntiles_own = (NTILES - bidx + gridx - 1) / gridx;
    const int pmax = ntiles_own * NCHUNK;

    // consumer geometry: 8 warps = 2 (M) x 4 (N); warp tile 64x48
    const int wm = wid & 1;
    const int wn = wid >> 1;
    const int laneRow = ((lane >> 3) & 1) * 8 + (lane & 7);
    const int laneG   = lane >> 4;
    const int rowAbase = wm * 64 + laneRow;
    const int rowBbase = wn * 48 + laneRow;

    // prologue (producers): preload positions 0,1; convert pos 0
    if (producer) {
        k4_load_pos(sbase, 0, bidx, gridx, Qf, E, pt);
        CP_ASYNC_COMMIT();
        k4_load_pos(sbase, 1, bidx, gridx, Qf, E, pt);
        CP_ASYNC_COMMIT();
        CP_ASYNC_WAIT_GROUP(1);
        PRODUCER_BAR();                 // cross-thread visibility of pos 0
        k4_convert(smem, 0, pt);
    }
    __syncthreads();

    int pc = 0;   // stream position being computed

#pragma unroll 1
    for (int j = 0; j < ntiles_own; j++) {
        const int T = bidx + j * gridx;
        const int m0 = (T & (NTILE_M - 1)) * 128;
        const int n0 = (T / NTILE_M) * TILE_N;

        float acc[4][6][4];
#pragma unroll
        for (int a = 0; a < 4; a++)
#pragma unroll
            for (int b = 0; b < 6; b++)
#pragma unroll
                for (int c = 0; c < 4; c++) acc[a][b][c] = 0.f;

#pragma unroll 1
        for (int i = 0; i < NCHUNK; i++) {
            if (!producer) {
                const uint32_t sA = sbase + AOFF + (uint32_t)(pc % 3) * A_TILE_B;
                const uint32_t sB = sbase + BOFF + (uint32_t)(pc & 1) * B16_TILE_B;
#pragma unroll
                for (int kh = 0; kh < 4; kh++) {
                    const uint32_t gof = (uint32_t)(kh * 32 + laneG * 16);
                    uint32_t a_op[4][4], b_op[3][4];
#pragma unroll
                    for (int mt = 0; mt < 4; mt++)
                        ldsm_x4(a_op[mt], sA + (uint32_t)((rowAbase + mt * 16) * 144) + gof);
#pragma unroll
                    for (int q = 0; q < 3; q++)
                        ldsm_x4(b_op[q], sB + (uint32_t)((rowBbase + q * 16) * 144) + gof);
#pragma unroll
                    for (int mt = 0; mt < 4; mt++)
#pragma unroll
                        for (int jj = 0; jj < 6; jj++)
                            mma_16816_f16(acc[mt][jj], a_op[mt],
                                          b_op[jj >> 1][jj & 1], b_op[jj >> 1][2 + (jj & 1)]);
                }
            } else {
                if (pc + 2 < pmax)
                    k4_load_pos(sbase, pc + 2, bidx, gridx, Qf, E, pt);
                CP_ASYNC_COMMIT();
                CP_ASYNC_WAIT_GROUP(1);
                PRODUCER_BAR();         // cross-thread visibility of pos pc+1
                if (pc + 1 < pmax)
                    k4_convert(smem, pc + 1, pt);
            }
            __syncthreads();
            pc++;
        }

        // Epilogue (consumers only; producers run ahead into next tile's loads)
        if (!producer) {
            const int erow = (lane >> 2);
            const int ecol = (lane & 3) * 2;
#pragma unroll
            for (int mt = 0; mt < 4; mt++) {
                const int r1 = m0 + wm * 64 + mt * 16 + erow;
#pragma unroll
                for (int jj = 0; jj < 6; jj++) {
                    const int n = n0 + wn * 48 + jj * 8 + ecol;
                    if (n < N_ENT) {
                        float2 v01 = make_float2(acc[mt][jj][0] * SCALE_OUT,
                                                 acc[mt][jj][1] * SCALE_OUT);
                        float2 v23 = make_float2(acc[mt][jj][2] * SCALE_OUT,
                                                 acc[mt][jj][3] * SCALE_OUT);
                        *(float2*)(C + (size_t)r1 * N_ENT + n) = v01;
                        *(float2*)(C + (size_t)(r1 + 8) * N_ENT + n) = v23;
                    }
                }
            }
        }
    }
}

// ---------------------------------------------------------------------------
extern "C" void kernel_launch(void* const* d_in, const int* in_sizes, int n_in,
                              void* d_out, int out_size)
{
    const int*   x      = (const int*)  d_in[0];
    const int*   nb_idx = (const int*)  d_in[1];
    const float* E_ent  = (const float*)d_in[2];
    const float* E_rel  = (const float*)d_in[3];
    const float* W0     = (const float*)d_in[4];
    const float* W1     = (const float*)d_in[5];
    const float* bw0    = (const float*)d_in[6];
    const float* bw1    = (const float*)d_in[7];
    const float* W20    = (const float*)d_in[8];
    const float* W21    = (const float*)d_in[9];
    const float* bw20   = (const float*)d_in[10];
    const float* bw21   = (const float*)d_in[11];
    const float* Uo0    = (const float*)d_in[12];
    const float* Uo1    = (const float*)d_in[13];
    const float* Wo0    = (const float*)d_in[14];
    const float* b_g    = (const float*)d_in[15];
    float* out = (float*)d_out;

    __half *Qf;
    cudaGetSymbolAddress((void**)&Qf, g_Qf);

    cudaFuncSetAttribute(k4_hmma, cudaFuncAttributeMaxDynamicSharedMemorySize, SMEM_K4);
    cudaFuncSetAttribute(k2_attn, cudaFuncAttributeMaxDynamicSharedMemorySize, K2_SMEM);

    int nsm = 148;
    cudaDeviceGetAttribute(&nsm, cudaDevAttrMultiProcessorCount, 0);

    k1_wproj  <<<(BATCH / K1_ROWS) * K1_SPLIT, 256>>>(x, E_ent, E_rel, W0, W1, bw0, bw1);
    k2_attn   <<<BATCH, 256, K2_SMEM>>>(nb_idx, E_ent);
    k3a_ecproj<<<(BATCH / K3_ROWS) * K3_SPLIT, 256>>>(W20, W21, bw20, bw21);
    k3b_gate_q<<<BATCH, 256>>>(x, E_ent, E_rel, Uo0, Uo1, Wo0, b_g, out);

    k4_hmma<<<nsm, K4_THREADS, SMEM_K4>>>(Qf, E_ent, out + OFF_SCORES);
}